// round 1
// baseline (speedup 1.0000x reference)
#include <cuda_runtime.h>
#include <math.h>

#define BB   32
#define SS   256
#define ISZ  1024
#define OSZ  1024
#define N4   4096
#define EPSF 1e-5f

// Scratch (static device globals -- no runtime allocation allowed)
__device__ float g_xproj[BB * SS * N4];   // 134 MB: x @ W_x + b, precomputed for all timesteps
__device__ float g_comb[BB * N4];         // per-step pre-LN activations
__device__ float g_h[BB * OSZ];
__device__ float g_c[BB * OSZ];

// ---------------------------------------------------------------------------
// Init h, c from init_hx / init_cx (broadcast over batch)
// ---------------------------------------------------------------------------
__global__ void init_state(const float* __restrict__ init_hx,
                           const float* __restrict__ init_cx) {
    int j = blockIdx.x * blockDim.x + threadIdx.x;
    if (j < BB * OSZ) {
        int i = j & (OSZ - 1);
        g_h[j] = init_hx[i];
        g_c[j] = init_cx[i];
    }
}

// ---------------------------------------------------------------------------
// xproj[row, n] = b[n] + sum_k x[row, k] * W[k, n]      row in [0, B*S)
// Block: (32, 8) threads. Each thread: 4 rows x 4 cols = 16 accumulators.
// Block tile: 32 rows x 128 cols. Grid: (4096/128, 8192/32) = (32, 256).
// ---------------------------------------------------------------------------
__global__ void xproj_kernel(const float* __restrict__ x,
                             const float* __restrict__ W,
                             const float* __restrict__ bias) {
    const int tx = threadIdx.x, ty = threadIdx.y;
    const int col0 = (blockIdx.x * 32 + tx) * 4;
    const int row0 = blockIdx.y * 32 + ty * 4;

    float acc[4][4] = {};
    const float* xp = x + (size_t)row0 * ISZ;

    #pragma unroll 4
    for (int k = 0; k < ISZ; k++) {
        float4 w = *(const float4*)(W + (size_t)k * N4 + col0);
        #pragma unroll
        for (int r = 0; r < 4; r++) {
            float xv = __ldg(xp + (size_t)r * ISZ + k);
            acc[r][0] += xv * w.x;
            acc[r][1] += xv * w.y;
            acc[r][2] += xv * w.z;
            acc[r][3] += xv * w.w;
        }
    }

    float4 bv = *(const float4*)(bias + col0);
    #pragma unroll
    for (int r = 0; r < 4; r++) {
        float4 o;
        o.x = acc[r][0] + bv.x;
        o.y = acc[r][1] + bv.y;
        o.z = acc[r][2] + bv.z;
        o.w = acc[r][3] + bv.w;
        *(float4*)(g_xproj + (size_t)(row0 + r) * N4 + col0) = o;
    }
}

// ---------------------------------------------------------------------------
// Per-step recurrent GEMM:
//   comb[b, n] = xproj[b*S + t, n] + sum_k h[b, k] * W[1024 + k, n]
// Block: (32, 8). col = bx*32 + tx (1 col/thread), rows = ty*4 .. ty*4+3.
// Grid: 128 blocks (4096 cols / 32). h rows stay hot in L1 (128 KB total).
// ---------------------------------------------------------------------------
__global__ void hgemm_kernel(const float* __restrict__ W, int t) {
    const int tx = threadIdx.x, ty = threadIdx.y;
    const int col = blockIdx.x * 32 + tx;
    const int row0 = ty * 4;
    const float* __restrict__ Wh = W + (size_t)ISZ * N4;

    float acc[4] = {};
    #pragma unroll 2
    for (int k = 0; k < ISZ; k += 4) {
        float w0 = __ldg(Wh + (size_t)(k + 0) * N4 + col);
        float w1 = __ldg(Wh + (size_t)(k + 1) * N4 + col);
        float w2 = __ldg(Wh + (size_t)(k + 2) * N4 + col);
        float w3 = __ldg(Wh + (size_t)(k + 3) * N4 + col);
        #pragma unroll
        for (int r = 0; r < 4; r++) {
            float4 hv = *(const float4*)(g_h + (size_t)(row0 + r) * OSZ + k);
            acc[r] += hv.x * w0 + hv.y * w1 + hv.z * w2 + hv.w * w3;
        }
    }

    #pragma unroll
    for (int r = 0; r < 4; r++) {
        int row = row0 + r;
        g_comb[(size_t)row * N4 + col] =
            acc[r] + g_xproj[((size_t)row * SS + t) * N4 + col];
    }
}

// ---------------------------------------------------------------------------
// LayerNorm over the 4096 gate pre-activations of each batch row, then the
// LSTM gate math. One block per batch row (32 blocks x 256 threads).
// NOTE reference: h = sigmoid(og) * c   (no tanh on c)
// ---------------------------------------------------------------------------
__global__ void ln_gate_kernel(const float* __restrict__ gamma,
                               const float* __restrict__ beta,
                               float* __restrict__ out, int t) {
    const int b   = blockIdx.x;
    const int tid = threadIdx.x;
    const float* __restrict__ comb = g_comb + (size_t)b * N4;

    // --- mean / var over 4096 elements ---
    float s = 0.f, ss = 0.f;
    #pragma unroll
    for (int i = tid; i < N4; i += 256) {
        float v = comb[i];
        s  += v;
        ss += v * v;
    }
    #pragma unroll
    for (int o = 16; o > 0; o >>= 1) {
        s  += __shfl_down_sync(0xffffffffu, s,  o);
        ss += __shfl_down_sync(0xffffffffu, ss, o);
    }
    __shared__ float sh_s[8], sh_ss[8];
    __shared__ float sh_mean, sh_rstd;
    int wid = tid >> 5, lane = tid & 31;
    if (lane == 0) { sh_s[wid] = s; sh_ss[wid] = ss; }
    __syncthreads();
    if (tid == 0) {
        float S_ = 0.f, SS_ = 0.f;
        #pragma unroll
        for (int w = 0; w < 8; w++) { S_ += sh_s[w]; SS_ += sh_ss[w]; }
        float mean = S_ * (1.0f / N4);
        float var  = SS_ * (1.0f / N4) - mean * mean;
        sh_mean = mean;
        sh_rstd = rsqrtf(var + EPSF);
    }
    __syncthreads();
    const float mean = sh_mean, rstd = sh_rstd;

    // --- gates ---
    #pragma unroll
    for (int i = tid; i < OSZ; i += 256) {
        float ig = (comb[0 * OSZ + i] - mean) * rstd * gamma[0 * OSZ + i] + beta[0 * OSZ + i];
        float fg = (comb[1 * OSZ + i] - mean) * rstd * gamma[1 * OSZ + i] + beta[1 * OSZ + i];
        float hd = (comb[2 * OSZ + i] - mean) * rstd * gamma[2 * OSZ + i] + beta[2 * OSZ + i];
        float og = (comb[3 * OSZ + i] - mean) * rstd * gamma[3 * OSZ + i] + beta[3 * OSZ + i];

        float sig_i = 1.f / (1.f + expf(-ig));
        float sig_f = 1.f / (1.f + expf(-fg));
        float sig_o = 1.f / (1.f + expf(-og));

        float c = sig_f * g_c[(size_t)b * OSZ + i] + sig_i * tanhf(hd);
        float h = sig_o * c;

        g_c[(size_t)b * OSZ + i] = c;
        g_h[(size_t)b * OSZ + i] = h;
        out[((size_t)b * SS + t) * OSZ + i] = h;
    }
}

// ---------------------------------------------------------------------------
// Launch: init -> xproj (one big GEMM) -> 256 x (hgemm -> ln_gate)
// Inputs (metadata order): x, W, b, gamma, beta, init_hx, init_cx
// ---------------------------------------------------------------------------
extern "C" void kernel_launch(void* const* d_in, const int* in_sizes, int n_in,
                              void* d_out, int out_size) {
    const float* x       = (const float*)d_in[0];
    const float* W       = (const float*)d_in[1];
    const float* bias    = (const float*)d_in[2];
    const float* gamma   = (const float*)d_in[3];
    const float* beta    = (const float*)d_in[4];
    const float* init_hx = (const float*)d_in[5];
    const float* init_cx = (const float*)d_in[6];
    float* out = (float*)d_out;

    init_state<<<(BB * OSZ + 255) / 256, 256>>>(init_hx, init_cx);

    dim3 blk(32, 8);
    xproj_kernel<<<dim3(32, 256), blk>>>(x, W, bias);

    for (int t = 0; t < SS; t++) {
        hgemm_kernel<<<128, blk>>>(W, t);
        ln_gate_kernel<<<BB, 256>>>(gamma, beta, out, t);
    }
}

// round 2
// speedup vs baseline: 2.4150x; 2.4150x over previous
#include <cuda_runtime.h>
#include <math.h>

#define BB   32
#define SS   256
#define ISZ  1024
#define OSZ  1024
#define N4   4096
#define EPSF 1e-5f
#define NBLK 128
#define NTHR 256

// Scratch (device globals -- no runtime allocation allowed)
__device__ float    g_xproj[BB * SS * N4];    // x @ W_x + b for all timesteps
__device__ float    g_h[BB * OSZ];            // hidden state (global, cross-block)
__device__ float    g_part[2][BB][NBLK];      // LN partial sums [stat][row][block]
__device__ unsigned g_bar;                    // grid barrier counter

// ---------------------------------------------------------------------------
// Init: h from init_hx (broadcast over batch), reset barrier
// ---------------------------------------------------------------------------
__global__ void init_state(const float* __restrict__ init_hx) {
    int j = blockIdx.x * blockDim.x + threadIdx.x;
    if (j == 0) g_bar = 0;
    if (j < BB * OSZ) g_h[j] = init_hx[j & (OSZ - 1)];
}

// ---------------------------------------------------------------------------
// xproj[row, n] = b[n] + sum_k x[row, k] * W[k, n]      row in [0, B*S)
// ---------------------------------------------------------------------------
__global__ void xproj_kernel(const float* __restrict__ x,
                             const float* __restrict__ W,
                             const float* __restrict__ bias) {
    const int tx = threadIdx.x, ty = threadIdx.y;
    const int col0 = (blockIdx.x * 32 + tx) * 4;
    const int row0 = blockIdx.y * 32 + ty * 4;

    float acc[4][4] = {};
    const float* xp = x + (size_t)row0 * ISZ;

    #pragma unroll 4
    for (int k = 0; k < ISZ; k++) {
        float4 w = *(const float4*)(W + (size_t)k * N4 + col0);
        #pragma unroll
        for (int r = 0; r < 4; r++) {
            float xv = __ldg(xp + (size_t)r * ISZ + k);
            acc[r][0] += xv * w.x;
            acc[r][1] += xv * w.y;
            acc[r][2] += xv * w.z;
            acc[r][3] += xv * w.w;
        }
    }

    float4 bv = *(const float4*)(bias + col0);
    #pragma unroll
    for (int r = 0; r < 4; r++) {
        float4 o;
        o.x = acc[r][0] + bv.x;
        o.y = acc[r][1] + bv.y;
        o.z = acc[r][2] + bv.z;
        o.w = acc[r][3] + bv.w;
        *(float4*)(g_xproj + (size_t)(row0 + r) * N4 + col0) = o;
    }
}

// ---------------------------------------------------------------------------
// Software grid barrier (all NBLK blocks co-resident: 1 block/SM by smem)
// ---------------------------------------------------------------------------
__device__ __forceinline__ void gsync(unsigned target) {
    __syncthreads();
    if (threadIdx.x == 0) {
        __threadfence();
        atomicAdd(&g_bar, 1u);
        while (*(volatile unsigned*)&g_bar < target) { }
        __threadfence();
    }
    __syncthreads();
}

// ---------------------------------------------------------------------------
// Persistent LSTM recurrence. Block `blk` owns output indices
// i = blk*8 .. blk*8+7 and their 4 gate columns {g*1024 + i}.
// W_h slice (1024 x 32 cols) cached in dynamic SMEM for all 256 steps.
// Thread (tx, ty): tx -> one of 32 cols (g = tx>>3, q = tx&7),
//                  ty -> batch rows ty*4 .. ty*4+3.
// ---------------------------------------------------------------------------
__global__ void __launch_bounds__(NTHR, 1)
lstm_persist(const float* __restrict__ W,
             const float* __restrict__ gamma,
             const float* __restrict__ beta,
             const float* __restrict__ init_cx,
             float* __restrict__ out) {
    extern __shared__ float Ws[];            // [1024][32]
    __shared__ float c_sm[BB * 8];           // cell state slice (b, q)

    const int tid = threadIdx.x;
    const int tx  = tid & 31, ty = tid >> 5;
    const int blk = blockIdx.x;
    const int g   = tx >> 3, q = tx & 7;
    const int gcol = g * OSZ + blk * 8 + q;  // column in [0, 4096)
    const int b0  = ty * 4;

    // Preload W_h slice: Ws[k*32 + c] = W[(ISZ+k)*N4 + colmap(c)]
    for (int idx = tid; idx < ISZ * 32; idx += NTHR) {
        int k = idx >> 5, c = idx & 31;
        int col = (c >> 3) * OSZ + blk * 8 + (c & 7);
        Ws[idx] = W[(size_t)(ISZ + k) * N4 + col];
    }
    // Init cell state slice from init_cx (broadcast over batch)
    if (tid < BB * 8)
        c_sm[tid] = init_cx[blk * 8 + (tid & 7)];

    const float gam = gamma[gcol];
    const float bet = beta[gcol];
    __syncthreads();

    unsigned nsync = 0;

    for (int t = 0; t < SS; t++) {
        // ---- recurrent GEMM: acc[r] = xproj + sum_k h[b0+r][k]*Ws[k][tx] ----
        float acc[4];
        #pragma unroll
        for (int r = 0; r < 4; r++)
            acc[r] = __ldg(&g_xproj[((size_t)(b0 + r) * SS + t) * N4 + gcol]);

        #pragma unroll 2
        for (int k = 0; k < ISZ; k += 8) {
            float4 hA[4], hB[4];
            #pragma unroll
            for (int r = 0; r < 4; r++) {
                hA[r] = __ldcg((const float4*)(g_h + (size_t)(b0 + r) * OSZ + k));
                hB[r] = __ldcg((const float4*)(g_h + (size_t)(b0 + r) * OSZ + k + 4));
            }
            float w[8];
            #pragma unroll
            for (int u = 0; u < 8; u++) w[u] = Ws[(k + u) * 32 + tx];
            #pragma unroll
            for (int r = 0; r < 4; r++) {
                acc[r] += hA[r].x * w[0] + hA[r].y * w[1] + hA[r].z * w[2] + hA[r].w * w[3]
                        + hB[r].x * w[4] + hB[r].y * w[5] + hB[r].z * w[6] + hB[r].w * w[7];
            }
        }

        // ---- LN partial sums over this block's 32 columns, per row ----
        float s[4], ss[4];
        #pragma unroll
        for (int r = 0; r < 4; r++) { s[r] = acc[r]; ss[r] = acc[r] * acc[r]; }
        #pragma unroll
        for (int o = 16; o > 0; o >>= 1) {
            #pragma unroll
            for (int r = 0; r < 4; r++) {
                s[r]  += __shfl_xor_sync(0xffffffffu, s[r],  o);
                ss[r] += __shfl_xor_sync(0xffffffffu, ss[r], o);
            }
        }
        if (tx == 0) {
            #pragma unroll
            for (int r = 0; r < 4; r++) {
                __stcg(&g_part[0][b0 + r][blk], s[r]);
                __stcg(&g_part[1][b0 + r][blk], ss[r]);
            }
        }

        gsync(++nsync * NBLK);

        // ---- aggregate stats (deterministic): warp ty handles rows b0..b0+3 ----
        float mean[4], rstd[4];
        #pragma unroll
        for (int r = 0; r < 4; r++) {
            int row = b0 + r;
            float4 sv = __ldcg((const float4*)&g_part[0][row][tx * 4]);
            float4 qv = __ldcg((const float4*)&g_part[1][row][tx * 4]);
            float sl = (sv.x + sv.y) + (sv.z + sv.w);
            float ql = (qv.x + qv.y) + (qv.z + qv.w);
            #pragma unroll
            for (int o = 16; o > 0; o >>= 1) {
                sl += __shfl_xor_sync(0xffffffffu, sl, o);
                ql += __shfl_xor_sync(0xffffffffu, ql, o);
            }
            float m = sl * (1.0f / N4);
            mean[r] = m;
            rstd[r] = rsqrtf(ql * (1.0f / N4) - m * m + EPSF);
        }

        // ---- LN + gates. The 4 gates of index i sit in lanes q, q+8, q+16, q+24 ----
        #pragma unroll
        for (int r = 0; r < 4; r++) {
            float v = (acc[r] - mean[r]) * rstd[r] * gam + bet;
            float a0 = __shfl_sync(0xffffffffu, v, q);        // ig
            float a1 = __shfl_sync(0xffffffffu, v, q + 8);    // fg
            float a2 = __shfl_sync(0xffffffffu, v, q + 16);   // hidden
            float a3 = __shfl_sync(0xffffffffu, v, q + 24);   // og
            if (g == 0) {
                int b = b0 + r;
                int i = blk * 8 + q;
                float si = 1.0f / (1.0f + expf(-a0));
                float sf = 1.0f / (1.0f + expf(-a1));
                float so = 1.0f / (1.0f + expf(-a3));
                float co = c_sm[b * 8 + q];
                float cn = sf * co + si * tanhf(a2);
                float h  = so * cn;
                c_sm[b * 8 + q] = cn;
                __stcg(&g_h[(size_t)b * OSZ + i], h);
                out[((size_t)b * SS + t) * OSZ + i] = h;
            }
        }

        gsync(++nsync * NBLK);
    }
}

// ---------------------------------------------------------------------------
// Inputs (metadata order): x, W, b, gamma, beta, init_hx, init_cx
// ---------------------------------------------------------------------------
extern "C" void kernel_launch(void* const* d_in, const int* in_sizes, int n_in,
                              void* d_out, int out_size) {
    const float* x       = (const float*)d_in[0];
    const float* W       = (const float*)d_in[1];
    const float* bias    = (const float*)d_in[2];
    const float* gamma   = (const float*)d_in[3];
    const float* beta    = (const float*)d_in[4];
    const float* init_hx = (const float*)d_in[5];
    const float* init_cx = (const float*)d_in[6];
    float* out = (float*)d_out;

    init_state<<<(BB * OSZ + 255) / 256, 256>>>(init_hx);

    dim3 blk(32, 8);
    xproj_kernel<<<dim3(32, 256), blk>>>(x, W, bias);

    cudaFuncSetAttribute(lstm_persist,
                         cudaFuncAttributeMaxDynamicSharedMemorySize, 131072);
    lstm_persist<<<NBLK, NTHR, 131072>>>(W, gamma, beta, init_cx, out);
}